// round 13
// baseline (speedup 1.0000x reference)
#include <cuda_runtime.h>
#include <cuda_bf16.h>

// RMLoss: pairwise Bradley-Terry loss over 4096 variable-length segments.
//   pair_loss(i<j) = softplus(x_j - x_i) + BETA*0.5*(x_i^2 + x_j^2)
//   seg = mean over pairs; output = mean over segments.
// L2 term collapses: sum over pairs of 0.5(xi^2+xj^2) = 0.5*(L-1)*sum(x^2).
//
// Pair enumeration uses the circulant ("rectangle") mapping: for offsets
// k = 1..floor((L-1)/2), the pairs {u, (u+k) mod L} for u = 0..L-1 cover each
// unordered pair exactly once (plus the k = L/2 half-row when L is even).
// This keeps all lanes of a warp active every iteration (vs. triangular rows).
// The wrap is split into two loops so there is no per-iteration select.

#define NSEG_MAX 4096
#define BETA   0.001f
#define LOG2E  1.44269504088896340736f
#define LN2    0.69314718055994530942f

__device__ float        g_seg[NSEG_MAX];
__device__ unsigned int g_count = 0;

__inline__ __device__ float warp_sum(float v) {
    #pragma unroll
    for (int o = 16; o; o >>= 1) v += __shfl_xor_sync(0xffffffffu, v, o);
    return v;
}

__global__ __launch_bounds__(128) void seg_kernel(
    const float* __restrict__ logits,
    const int*   __restrict__ cu32,   // int32 view of cu_lengths (int32 or int64)
    float*       __restrict__ out,
    int ns)
{
    // Detect dtype layout: cu[0]==0 always; for little-endian int64, word[1]
    // is the high half of cu[0] == 0. For int32, word[1] = cu[1] >= 32.
    const int stride = (cu32[1] == 0) ? 2 : 1;

    const int s = blockIdx.x;
    const int a = cu32[s * stride];
    const int b = cu32[(s + 1) * stride];
    const int L = b - a;

    __shared__ float y[128];     // logits * log2(e)
    __shared__ float red[8];
    __shared__ int   lastflag;

    const int t = threadIdx.x;

    for (int k = t; k < L; k += 128) y[k] = logits[a + k] * LOG2E;
    __syncthreads();

    float lacc = 0.0f;   // sum of log2(1 + exp2(-|d|))   (log2 units)
    float macc = 0.0f;   // sum of max(d, 0)              (log2 units)
    float sq   = 0.0f;   // sum of y^2                    (log2^2 units)

    const int K = (L - 1) >> 1;

    if (t < L) {
        const float yu = y[t];
        sq = yu * yu;

        // Loop A: unwrapped offsets, v = t+k for k = 1..min(K, L-1-t)
        const int kA = min(K, L - 1 - t);
        #pragma unroll 4
        for (int k = 1; k <= kA; ++k) {
            float d = y[t + k] - yu;               // x_later - x_earlier
            float e = exp2f(-fabsf(d));            // single MUFU EX2
            lacc += __log2f(1.0f + e);
            macc += fmaxf(d, 0.0f);
        }

        // Loop B: wrapped offsets, v = 0..(K - (L - t)); earlier index is v
        const int nB = K - (L - t);
        #pragma unroll 4
        for (int v = 0; v <= nB; ++v) {
            float d = yu - y[v];                   // x_later - x_earlier
            float e = exp2f(-fabsf(d));
            lacc += __log2f(1.0f + e);
            macc += fmaxf(d, 0.0f);
        }

        // L even: offset L/2 row counted once (u < L/2 only)
        if ((L & 1) == 0 && t < (L >> 1)) {
            float d = y[t + (L >> 1)] - yu;
            float e = exp2f(-fabsf(d));
            lacc += __log2f(1.0f + e);
            macc += fmaxf(d, 0.0f);
        }
    }

    // Block reduce (4 warps): pair term and square term
    float p = lacc + macc;
    p  = warp_sum(p);
    sq = warp_sum(sq);
    const int lane = t & 31, wid = t >> 5;
    if (lane == 0) { red[wid] = p; red[wid + 4] = sq; }
    __syncthreads();

    if (t == 0) {
        float ps = red[0] + red[1] + red[2] + red[3];
        float qs = red[4] + red[5] + red[6] + red[7];
        float pair_sum = ps * LN2;                       // back to natural units
        float sqx      = qs * (LN2 * LN2);               // y^2 -> x^2
        float nPairs   = 0.5f * (float)L * (float)(L - 1);
        float total    = pair_sum + BETA * 0.5f * (float)(L - 1) * sqx;
        g_seg[s] = total / nPairs;
        __threadfence();
        unsigned int old = atomicAdd(&g_count, 1u);
        lastflag = (old == (unsigned int)(ns - 1));
    }
    __syncthreads();

    // Last block to finish performs the deterministic final reduction.
    if (lastflag) {
        __threadfence();
        float acc = 0.0f;
        for (int i = t; i < ns; i += 128) acc += g_seg[i];
        acc = warp_sum(acc);
        if (lane == 0) red[wid] = acc;
        __syncthreads();
        if (t == 0) {
            out[0] = (red[0] + red[1] + red[2] + red[3]) / (float)ns;
            g_count = 0;   // reset for next launch / graph replay
        }
    }
}

extern "C" void kernel_launch(void* const* d_in, const int* in_sizes, int n_in,
                              void* d_out, int out_size) {
    const float* logits = (const float*)d_in[0];
    const int*   cu32   = (const int*)d_in[1];

    // Number of segments: in_sizes[1] counts elements of cu_lengths (4097).
    // If the harness reported int64 as int32 words (8194), halve it.
    int ncu = in_sizes[1];
    int ns  = ncu - 1;
    if (ns > NSEG_MAX) ns = ncu / 2 - 1;
    if (ns > NSEG_MAX) ns = NSEG_MAX;

    seg_kernel<<<ns, 128>>>(logits, cu32, (float*)d_out, ns);
}

// round 14
// speedup vs baseline: 1.2405x; 1.2405x over previous
#include <cuda_runtime.h>
#include <cuda_bf16.h>

// RMLoss: pairwise Bradley-Terry loss over 4096 variable-length segments.
//   pair_loss(i<j) = softplus(x_j - x_i) + BETA*0.5*(x_i^2 + x_j^2)
//   seg = mean over pairs; output = mean over segments.
//
// Algebra used:
//   L2 term:   sum_pairs 0.5(xi^2+xj^2) = 0.5*(L-1)*sum(x^2)
//   softplus:  sum_pairs softplus(d) = 0.5*sum(d) + 0.5*sum|d| + sum ln(1+e^-|d|)
//              with sum_pairs d = sum_j x_j*(2j-L+1)   (O(L) linear term)
//   => the O(L^2) loop is pair-order independent (|d| only): uniform trip count.
//
// Pair enumeration: circulant offsets k=1..(L-1)/2 over all u (each unordered
// pair exactly once; +half row k=L/2 for even L). The segment is stored twice
// in shared memory so v=u+k never wraps: the inner loop is LDS [r+imm] with no
// per-iteration index arithmetic and no intra-warp divergence.

#define NSEG_MAX 4096
#define BETA   0.001f
#define LOG2E  1.44269504088896340736f
#define LN2    0.69314718055994530942f

__device__ float        g_seg[NSEG_MAX];
__device__ unsigned int g_count = 0;

__inline__ __device__ float warp_sum(float v) {
    #pragma unroll
    for (int o = 16; o; o >>= 1) v += __shfl_xor_sync(0xffffffffu, v, o);
    return v;
}

__global__ __launch_bounds__(128) void seg_kernel(
    const float* __restrict__ logits,
    const int*   __restrict__ cu32,   // int32 view of cu_lengths (int32 or int64)
    float*       __restrict__ out,
    int ns)
{
    // Detect dtype layout: cu[0]==0 always; for little-endian int64, word[1]
    // is the high half of cu[0] == 0. For int32, word[1] = cu[1] >= 32.
    const int stride = (cu32[1] == 0) ? 2 : 1;

    const int s = blockIdx.x;
    const int a = cu32[s * stride];
    const int b = cu32[(s + 1) * stride];
    const int L = b - a;            // 32 <= L <= 127

    __shared__ float y2[256];       // segment duplicated: y2[k] = y2[k+L]
    __shared__ float red[8];
    __shared__ int   lastflag;

    const int t = threadIdx.x;

    float sq  = 0.0f;               // y^2 contribution (log2^2 units)
    float lin = 0.0f;               // y * (2j - L + 1)  (log2 units)
    if (t < L) {
        float v = logits[a + t] * LOG2E;
        y2[t]     = v;
        y2[t + L] = v;
        sq  = v * v;
        lin = v * (float)(2 * t - L + 1);
    }
    __syncthreads();

    float lacc = 0.0f;              // sum log2(1 + 2^-|d|)
    float aacc = 0.0f;              // sum |d|

    const int K = (L - 1) >> 1;

    if (t < L) {
        const float yu = y2[t];
        // Uniform trip count for ALL lanes; addresses are [t+1 .. t+K], no wrap.
        #pragma unroll 4
        for (int k = 1; k <= K; ++k) {
            float d  = y2[t + k] - yu;
            float ad = fabsf(d);
            lacc += __log2f(1.0f + exp2f(-ad));   // 2x MUFU, modifiers folded
            aacc += ad;
        }
        // Even L: offset L/2 row, counted once (u < L/2 only)
        if ((L & 1) == 0 && t < (L >> 1)) {
            float d  = y2[t + (L >> 1)] - yu;
            float ad = fabsf(d);
            lacc += __log2f(1.0f + exp2f(-ad));
            aacc += ad;
        }
    }

    // Combine per-thread terms: p = lacc + 0.5*(|d| sum + linear term)
    float p = lacc + 0.5f * (aacc + lin);
    p  = warp_sum(p);
    sq = warp_sum(sq);
    const int lane = t & 31, wid = t >> 5;
    if (lane == 0) { red[wid] = p; red[wid + 4] = sq; }
    __syncthreads();

    if (t == 0) {
        float ps = red[0] + red[1] + red[2] + red[3];
        float qs = red[4] + red[5] + red[6] + red[7];
        float pair_sum = ps * LN2;                  // log2 units -> natural
        float sqx      = qs * (LN2 * LN2);          // y^2 -> x^2
        float nPairs   = 0.5f * (float)L * (float)(L - 1);
        float total    = pair_sum + BETA * 0.5f * (float)(L - 1) * sqx;
        g_seg[s] = total / nPairs;
        __threadfence();
        unsigned int old = atomicAdd(&g_count, 1u);
        lastflag = (old == (unsigned int)(ns - 1));
    }
    __syncthreads();

    // Last block to finish performs the deterministic final reduction.
    if (lastflag) {
        __threadfence();
        float acc = 0.0f;
        for (int i = t; i < ns; i += 128) acc += g_seg[i];
        acc = warp_sum(acc);
        if (lane == 0) red[wid] = acc;
        __syncthreads();
        if (t == 0) {
            out[0] = (red[0] + red[1] + red[2] + red[3]) / (float)ns;
            g_count = 0;   // reset for next launch / graph replay
        }
    }
}

extern "C" void kernel_launch(void* const* d_in, const int* in_sizes, int n_in,
                              void* d_out, int out_size) {
    const float* logits = (const float*)d_in[0];
    const int*   cu32   = (const int*)d_in[1];

    // Number of segments: in_sizes[1] counts elements of cu_lengths (4097).
    // If the harness reported int64 as int32 words (8194), halve it.
    int ncu = in_sizes[1];
    int ns  = ncu - 1;
    if (ns > NSEG_MAX) ns = ncu / 2 - 1;
    if (ns > NSEG_MAX) ns = NSEG_MAX;

    seg_kernel<<<ns, 128>>>(logits, cu32, (float*)d_out, ns);
}

// round 15
// speedup vs baseline: 1.4116x; 1.1379x over previous
#include <cuda_runtime.h>
#include <cuda_bf16.h>

// RMLoss: pairwise Bradley-Terry loss over 4096 variable-length segments.
//   pair_loss(i<j) = softplus(x_j - x_i) + BETA*0.5*(x_i^2 + x_j^2)
//   seg = mean over pairs; output = mean over segments.
//
// Algebra used:
//   L2 term:   sum_pairs 0.5(xi^2+xj^2) = 0.5*(L-1)*sum(x^2)
//   softplus:  sum_pairs softplus(d) = 0.5*sum(d) + 0.5*sum|d| + sum ln(1+e^-|d|)
//              with sum_pairs d = sum_j x_j*(2j-L+1)   (O(L) linear term)
//   product:   sum_i log2(1+e_i) = log2( prod_i (1+e_i) )  -> ONE LG2 per
//              thread instead of one per pair. Factors are in (1,2]; per-
//              accumulator product <= 2^33 (two alternating accumulators,
//              K <= 63), far below float overflow; rounding ~1e-5 relative
//              on the product -> ~2e-5 absolute in log2 units. Negligible.
//   per-pair:  d (FADD), e = exp2(-|d|) (1 MUFU, modifiers folded),
//              prod = fmaf(prod, e, prod)  == prod*(1+e)  (1 FFMA),
//              aacc += |d| (FADD).  MUFU-bound at 8 cyc/warp-pair.
//
// Pair enumeration: circulant offsets k=1..(L-1)/2 over all u (each unordered
// pair exactly once; +half row k=L/2 for even L). The segment is stored twice
// in shared memory so v=u+k never wraps: uniform trip count, no divergence.

#define NSEG_MAX 4096
#define BETA   0.001f
#define LOG2E  1.44269504088896340736f
#define LN2    0.69314718055994530942f

__device__ float        g_seg[NSEG_MAX];
__device__ unsigned int g_count = 0;

__inline__ __device__ float warp_sum(float v) {
    #pragma unroll
    for (int o = 16; o; o >>= 1) v += __shfl_xor_sync(0xffffffffu, v, o);
    return v;
}

__global__ __launch_bounds__(128) void seg_kernel(
    const float* __restrict__ logits,
    const int*   __restrict__ cu32,   // int32 view of cu_lengths (int32 or int64)
    float*       __restrict__ out,
    int ns)
{
    // Detect dtype layout: cu[0]==0 always; for little-endian int64, word[1]
    // is the high half of cu[0] == 0. For int32, word[1] = cu[1] >= 32.
    const int stride = (cu32[1] == 0) ? 2 : 1;

    const int s = blockIdx.x;
    const int a = cu32[s * stride];
    const int b = cu32[(s + 1) * stride];
    const int L = b - a;            // 32 <= L <= 127

    __shared__ float y2[256];       // segment duplicated: y2[k] = y2[k+L]
    __shared__ float red[8];
    __shared__ int   lastflag;

    const int t = threadIdx.x;

    float sq  = 0.0f;               // y^2 contribution (log2^2 units)
    float lin = 0.0f;               // y * (2j - L + 1)  (log2 units)
    if (t < L) {
        float v = logits[a + t] * LOG2E;
        y2[t]     = v;
        y2[t + L] = v;
        sq  = v * v;
        lin = v * (float)(2 * t - L + 1);
    }
    __syncthreads();

    float lacc = 0.0f;              // sum log2(1 + 2^-|d|)  (via product)
    float aacc = 0.0f;              // sum |d|

    const int K = (L - 1) >> 1;

    if (t < L) {
        const float yu = y2[t];
        float p0 = 1.0f, p1 = 1.0f;      // alternating product accumulators
        float a0 = 0.0f, a1 = 0.0f;
        // Uniform trip count for ALL lanes; addresses [t+1 .. t+K], no wrap.
        #pragma unroll 4
        for (int k = 1; k + 1 <= K; k += 2) {
            float d0  = y2[t + k]     - yu;
            float d1  = y2[t + k + 1] - yu;
            float e0  = exp2f(-fabsf(d0));   // MUFU.EX2, -|.| folded
            float e1  = exp2f(-fabsf(d1));
            p0 = fmaf(p0, e0, p0);           // p0 *= (1 + e0)
            p1 = fmaf(p1, e1, p1);
            a0 += fabsf(d0);
            a1 += fabsf(d1);
        }
        if (K & 1) {                          // K odd: last offset
            float d  = y2[t + K] - yu;
            float e  = exp2f(-fabsf(d));
            p0 = fmaf(p0, e, p0);
            a0 += fabsf(d);
        }
        // Even L: offset L/2 row, counted once (u < L/2 only)
        if ((L & 1) == 0 && t < (L >> 1)) {
            float d  = y2[t + (L >> 1)] - yu;
            float e  = exp2f(-fabsf(d));
            p1 = fmaf(p1, e, p1);
            a1 += fabsf(d);
        }
        lacc = __log2f(p0) + __log2f(p1);    // 2 MUFU per THREAD total
        aacc = a0 + a1;
    }

    // Combine per-thread terms: p = lacc + 0.5*(|d| sum + linear term)
    float p = lacc + 0.5f * (aacc + lin);
    p  = warp_sum(p);
    sq = warp_sum(sq);
    const int lane = t & 31, wid = t >> 5;
    if (lane == 0) { red[wid] = p; red[wid + 4] = sq; }
    __syncthreads();

    if (t == 0) {
        float ps = red[0] + red[1] + red[2] + red[3];
        float qs = red[4] + red[5] + red[6] + red[7];
        float pair_sum = ps * LN2;                  // log2 units -> natural
        float sqx      = qs * (LN2 * LN2);          // y^2 -> x^2
        float nPairs   = 0.5f * (float)L * (float)(L - 1);
        float total    = pair_sum + BETA * 0.5f * (float)(L - 1) * sqx;
        g_seg[s] = total / nPairs;
        __threadfence();
        unsigned int old = atomicAdd(&g_count, 1u);
        lastflag = (old == (unsigned int)(ns - 1));
    }
    __syncthreads();

    // Last block to finish performs the deterministic final reduction.
    if (lastflag) {
        __threadfence();
        float acc = 0.0f;
        for (int i = t; i < ns; i += 128) acc += g_seg[i];
        acc = warp_sum(acc);
        if (lane == 0) red[wid] = acc;
        __syncthreads();
        if (t == 0) {
            out[0] = (red[0] + red[1] + red[2] + red[3]) / (float)ns;
            g_count = 0;   // reset for next launch / graph replay
        }
    }
}

extern "C" void kernel_launch(void* const* d_in, const int* in_sizes, int n_in,
                              void* d_out, int out_size) {
    const float* logits = (const float*)d_in[0];
    const int*   cu32   = (const int*)d_in[1];

    // Number of segments: in_sizes[1] counts elements of cu_lengths (4097).
    // If the harness reported int64 as int32 words (8194), halve it.
    int ncu = in_sizes[1];
    int ns  = ncu - 1;
    if (ns > NSEG_MAX) ns = ncu / 2 - 1;
    if (ns > NSEG_MAX) ns = NSEG_MAX;

    seg_kernel<<<ns, 128>>>(logits, cu32, (float*)d_out, ns);
}

// round 16
// speedup vs baseline: 1.6375x; 1.1600x over previous
#include <cuda_runtime.h>
#include <cuda_bf16.h>

// RMLoss: pairwise Bradley-Terry loss over 4096 variable-length segments.
//   pair_loss(i<j) = softplus(x_j - x_i) + BETA*0.5*(x_i^2 + x_j^2)
//   seg = mean over pairs; output = mean over segments.
//
// Algebra used:
//   L2 term:   sum_pairs 0.5(xi^2+xj^2) = 0.5*(L-1)*sum(x^2)
//   softplus:  sum_pairs softplus(d) = 0.5*sum(d) + 0.5*sum|d| + sum ln(1+e^-|d|)
//              with sum_pairs d = sum_j x_j*(2j-L+1)   (O(L) linear term)
//   product:   sum_i log2(1+e_i) = log2( prod_i (1+e_i) )  -> ONE LG2 per
//              thread instead of one per pair. Factors in (1,2]; per-
//              accumulator product <= 2^33 (two alternating accumulators).
//   per-pair:  LDS, FADD(d), MUFU.EX2(-|d| via folded modifiers),
//              FFMA(prod*(1+e)), FADD(|d|)  ->  ~5 issues/pair.
//
// exp2/log2 go through inline PTX ex2.approx/lg2.approx: the standard
// exp2f() expands to a multi-instruction accurate sequence (no __exp2f
// intrinsic exists); the raw MUFU op is 1 instruction and ~2^-22 accurate,
// far inside the 1e-3 rel_err budget.
//
// Pair enumeration: circulant offsets k=1..(L-1)/2 over all u (each unordered
// pair exactly once; +half row k=L/2 for even L). The segment is stored twice
// in shared memory so v=u+k never wraps: uniform trip count, no divergence.

#define NSEG_MAX 4096
#define BETA   0.001f
#define LOG2E  1.44269504088896340736f
#define LN2    0.69314718055994530942f

__device__ float        g_seg[NSEG_MAX];
__device__ unsigned int g_count = 0;

__device__ __forceinline__ float ex2_fast(float x) {
    float r; asm("ex2.approx.ftz.f32 %0, %1;" : "=f"(r) : "f"(x)); return r;
}
__device__ __forceinline__ float lg2_fast(float x) {
    float r; asm("lg2.approx.ftz.f32 %0, %1;" : "=f"(r) : "f"(x)); return r;
}

__inline__ __device__ float warp_sum(float v) {
    #pragma unroll
    for (int o = 16; o; o >>= 1) v += __shfl_xor_sync(0xffffffffu, v, o);
    return v;
}

__global__ __launch_bounds__(128) void seg_kernel(
    const float* __restrict__ logits,
    const int*   __restrict__ cu32,   // int32 view of cu_lengths (int32 or int64)
    float*       __restrict__ out,
    int ns)
{
    // Detect dtype layout: cu[0]==0 always; for little-endian int64, word[1]
    // is the high half of cu[0] == 0. For int32, word[1] = cu[1] >= 32.
    const int stride = (cu32[1] == 0) ? 2 : 1;

    const int s = blockIdx.x;
    const int a = cu32[s * stride];
    const int b = cu32[(s + 1) * stride];
    const int L = b - a;            // 32 <= L <= 127

    __shared__ float y2[256];       // segment duplicated: y2[k] = y2[k+L]
    __shared__ float red[8];
    __shared__ int   lastflag;

    const int t = threadIdx.x;

    float sq  = 0.0f;               // y^2 contribution (log2^2 units)
    float lin = 0.0f;               // y * (2j - L + 1)  (log2 units)
    if (t < L) {
        float v = logits[a + t] * LOG2E;
        y2[t]     = v;
        y2[t + L] = v;
        sq  = v * v;
        lin = v * (float)(2 * t - L + 1);
    }
    __syncthreads();

    float lacc = 0.0f;              // sum log2(1 + 2^-|d|)  (via product)
    float aacc = 0.0f;              // sum |d|

    const int K = (L - 1) >> 1;

    if (t < L) {
        const float yu = y2[t];
        float p0 = 1.0f, p1 = 1.0f;      // alternating product accumulators
        float a0 = 0.0f, a1 = 0.0f;
        // Uniform trip count for ALL lanes; addresses [t+1 .. t+K], no wrap.
        #pragma unroll 4
        for (int k = 1; k + 1 <= K; k += 2) {
            float d0  = y2[t + k]     - yu;
            float d1  = y2[t + k + 1] - yu;
            float e0  = ex2_fast(-fabsf(d0));   // single MUFU.EX2
            float e1  = ex2_fast(-fabsf(d1));
            p0 = fmaf(p0, e0, p0);              // p0 *= (1 + e0)
            p1 = fmaf(p1, e1, p1);
            a0 += fabsf(d0);
            a1 += fabsf(d1);
        }
        if (K & 1) {                             // K odd: last offset
            float d  = y2[t + K] - yu;
            float e  = ex2_fast(-fabsf(d));
            p0 = fmaf(p0, e, p0);
            a0 += fabsf(d);
        }
        // Even L: offset L/2 row, counted once (u < L/2 only)
        if ((L & 1) == 0 && t < (L >> 1)) {
            float d  = y2[t + (L >> 1)] - yu;
            float e  = ex2_fast(-fabsf(d));
            p1 = fmaf(p1, e, p1);
            a1 += fabsf(d);
        }
        lacc = lg2_fast(p0) + lg2_fast(p1);      // 2 MUFU per THREAD total
        aacc = a0 + a1;
    }

    // Combine per-thread terms: p = lacc + 0.5*(|d| sum + linear term)
    float p = lacc + 0.5f * (aacc + lin);
    p  = warp_sum(p);
    sq = warp_sum(sq);
    const int lane = t & 31, wid = t >> 5;
    if (lane == 0) { red[wid] = p; red[wid + 4] = sq; }
    __syncthreads();

    if (t == 0) {
        float ps = red[0] + red[1] + red[2] + red[3];
        float qs = red[4] + red[5] + red[6] + red[7];
        float pair_sum = ps * LN2;                  // log2 units -> natural
        float sqx      = qs * (LN2 * LN2);          // y^2 -> x^2
        float nPairs   = 0.5f * (float)L * (float)(L - 1);
        float total    = pair_sum + BETA * 0.5f * (float)(L - 1) * sqx;
        g_seg[s] = total / nPairs;
        __threadfence();
        unsigned int old = atomicAdd(&g_count, 1u);
        lastflag = (old == (unsigned int)(ns - 1));
    }
    __syncthreads();

    // Last block to finish performs the deterministic final reduction.
    if (lastflag) {
        __threadfence();
        float acc = 0.0f;
        for (int i = t; i < ns; i += 128) acc += g_seg[i];
        acc = warp_sum(acc);
        if (lane == 0) red[wid] = acc;
        __syncthreads();
        if (t == 0) {
            out[0] = (red[0] + red[1] + red[2] + red[3]) / (float)ns;
            g_count = 0;   // reset for next launch / graph replay
        }
    }
}

extern "C" void kernel_launch(void* const* d_in, const int* in_sizes, int n_in,
                              void* d_out, int out_size) {
    const float* logits = (const float*)d_in[0];
    const int*   cu32   = (const int*)d_in[1];

    // Number of segments: in_sizes[1] counts elements of cu_lengths (4097).
    // If the harness reported int64 as int32 words (8194), halve it.
    int ncu = in_sizes[1];
    int ns  = ncu - 1;
    if (ns > NSEG_MAX) ns = ncu / 2 - 1;
    if (ns > NSEG_MAX) ns = NSEG_MAX;

    seg_kernel<<<ns, 128>>>(logits, cu32, (float*)d_out, ns);
}